// round 2
// baseline (speedup 1.0000x reference)
#include <cuda_runtime.h>
#include <cstdint>

#define BB   64
#define TT   4096
#define NIN  64
#define UU   128
#define NOUT 64
#define BC   16      // batch rows per CTA
#define CHUNK 111    // timesteps per chunk
#define HALO  48     // warm-up steps (||AT^48|| ~ 1e-12, exact at fp32)
#define NCHUNK 37    // 37*111 = 4107 >= 4096

#define XS 68        // xbuf row stride (words), padded for conflict-free frag loads
#define SS 132       // sbuf row stride (words)

__device__ __forceinline__ uint32_t f2tf(float f) {
    uint32_t u;
    asm("cvt.rna.tf32.f32 %0, %1;" : "=r"(u) : "f"(f));
    return u;
}

__device__ __forceinline__ void mma8(float c[4], const uint32_t a[4], const uint32_t b[2]) {
    asm volatile(
        "mma.sync.aligned.m16n8k8.row.col.f32.tf32.tf32.f32 "
        "{%0,%1,%2,%3}, {%4,%5,%6,%7}, {%8,%9}, {%0,%1,%2,%3};"
        : "+f"(c[0]), "+f"(c[1]), "+f"(c[2]), "+f"(c[3])
        : "r"(a[0]), "r"(a[1]), "r"(a[2]), "r"(a[3]), "r"(b[0]), "r"(b[1]));
}

__global__ __launch_bounds__(256, 1) void rnn_scan_kernel(
    const float* __restrict__ x,    // [B, T, NIN]
    const float* __restrict__ AT,   // [U, U]
    const float* __restrict__ KT,   // [NIN, U]
    const float* __restrict__ CyT,  // [U, NOUT]
    float* __restrict__ Y)          // [B, T, NOUT]
{
    __shared__ uint32_t sbuf[2][BC][SS];  // state S_{t-1} as tf32, double-buffered
    __shared__ uint32_t xbuf[2][BC][XS];  // x_t as tf32, double-buffered

    const int tid  = threadIdx.x;
    const int w    = tid >> 5;
    const int lane = tid & 31;
    const int g    = lane >> 2;   // groupID (row within fragment)
    const int tig  = lane & 3;    // threadID in group (col within fragment)

    const int t0      = blockIdx.x * CHUNK;
    const int t_end   = min(t0 + CHUNK, TT);
    const int t_start = max(0, t0 - HALO);
    const int b0      = blockIdx.y * BC;

    // ---- persistent weight fragments (tf32, registers) ----
    // AT used as B operand of S*AT : b0=(k=kt*8+tig, n=col), b1=(k+4, col)
    uint32_t Af[16][2][2];   // 16 k-tiles x 2 n-tiles (warp owns 16 U-cols)
    uint32_t Kf[8][2][2];    // KT: 8 k-tiles (K=64) x 2 n-tiles
    uint32_t Cf[16][2];      // CyT: 16 k-tiles x 1 n-tile (warp owns 8 out-cols)
    #pragma unroll
    for (int kt = 0; kt < 16; ++kt)
        #pragma unroll
        for (int nt = 0; nt < 2; ++nt) {
            int col = w * 16 + nt * 8 + g;
            Af[kt][nt][0] = f2tf(AT[(kt * 8 + tig) * UU + col]);
            Af[kt][nt][1] = f2tf(AT[(kt * 8 + tig + 4) * UU + col]);
        }
    #pragma unroll
    for (int kt = 0; kt < 8; ++kt)
        #pragma unroll
        for (int nt = 0; nt < 2; ++nt) {
            int col = w * 16 + nt * 8 + g;
            Kf[kt][nt][0] = f2tf(KT[(kt * 8 + tig) * UU + col]);
            Kf[kt][nt][1] = f2tf(KT[(kt * 8 + tig + 4) * UU + col]);
        }
    #pragma unroll
    for (int kt = 0; kt < 16; ++kt) {
        int col = w * 8 + g;
        Cf[kt][0] = f2tf(CyT[(kt * 8 + tig) * NOUT + col]);
        Cf[kt][1] = f2tf(CyT[(kt * 8 + tig + 4) * NOUT + col]);
    }

    // ---- zero initial state (S_{t_start-1} = 0; exact for chunk 0, halo-exact otherwise) ----
    {
        uint32_t* z = &sbuf[0][0][0];
        for (int i = tid; i < BC * SS; i += 256) z[i] = 0;
    }

    // ---- preload x(t_start) into xbuf ----
    const int xr = tid >> 4;          // 0..15 batch row
    const int xc = (tid & 15) * 4;    // 0..60 col (float4)
    float4 xv;
    {
        int addr = ((b0 + xr) * TT + t_start) * NIN + xc;
        xv = *reinterpret_cast<const float4*>(x + addr);
        uint32_t* d = &xbuf[t_start & 1][xr][xc];
        d[0] = f2tf(xv.x); d[1] = f2tf(xv.y); d[2] = f2tf(xv.z); d[3] = f2tf(xv.w);
    }
    __syncthreads();

    int p  = 0;                  // state buffer phase
    int xp = t_start & 1;        // x buffer phase
    for (int t = t_start; t <= t_end; ++t) {
        const bool compute_s = (t < t_end);      // block-uniform
        const bool do_y      = (t > t0);         // block-uniform

        // prefetch x(t+1) from global (latency hidden under the mma loop)
        if (t + 1 < t_end) {
            int addr = ((b0 + xr) * TT + (t + 1)) * NIN + xc;
            xv = *reinterpret_cast<const float4*>(x + addr);
        }

        float sacc[2][4] = {{0.f,0.f,0.f,0.f},{0.f,0.f,0.f,0.f}};
        float yacc[4]    = {0.f,0.f,0.f,0.f};

        // S_t += x_t * KT
        if (compute_s) {
            #pragma unroll
            for (int kt = 0; kt < 8; ++kt) {
                uint32_t a[4];
                a[0] = xbuf[xp][g    ][kt * 8 + tig];
                a[1] = xbuf[xp][g + 8][kt * 8 + tig];
                a[2] = xbuf[xp][g    ][kt * 8 + tig + 4];
                a[3] = xbuf[xp][g + 8][kt * 8 + tig + 4];
                mma8(sacc[0], a, Kf[kt][0]);
                mma8(sacc[1], a, Kf[kt][1]);
            }
        }

        // S_t += S_{t-1} * AT   and   Y_{t-1} = S_{t-1} * CyT
        #pragma unroll
        for (int kt = 0; kt < 16; ++kt) {
            uint32_t a[4];
            a[0] = sbuf[p][g    ][kt * 8 + tig];
            a[1] = sbuf[p][g + 8][kt * 8 + tig];
            a[2] = sbuf[p][g    ][kt * 8 + tig + 4];
            a[3] = sbuf[p][g + 8][kt * 8 + tig + 4];
            if (compute_s) { mma8(sacc[0], a, Af[kt][0]); mma8(sacc[1], a, Af[kt][1]); }
            if (do_y)      { mma8(yacc, a, Cf[kt]); }
        }

        // store Y_{t-1}
        if (do_y) {
            int base = ((b0 + g) * TT + (t - 1)) * NOUT + w * 8 + 2 * tig;
            *reinterpret_cast<float2*>(Y + base) = make_float2(yacc[0], yacc[1]);
            *reinterpret_cast<float2*>(Y + base + 8 * TT * NOUT) = make_float2(yacc[2], yacc[3]);
        }

        if (compute_s) {
            // store S_t (tf32) into the other state buffer
            #pragma unroll
            for (int nt = 0; nt < 2; ++nt) {
                int col = w * 16 + nt * 8 + 2 * tig;
                uint32_t* d0 = &sbuf[p ^ 1][g][col];
                d0[0] = f2tf(sacc[nt][0]); d0[1] = f2tf(sacc[nt][1]);
                uint32_t* d1 = &sbuf[p ^ 1][g + 8][col];
                d1[0] = f2tf(sacc[nt][2]); d1[1] = f2tf(sacc[nt][3]);
            }
            // store prefetched x(t+1)
            if (t + 1 < t_end) {
                uint32_t* d = &xbuf[xp ^ 1][xr][xc];
                d[0] = f2tf(xv.x); d[1] = f2tf(xv.y); d[2] = f2tf(xv.z); d[3] = f2tf(xv.w);
            }
            __syncthreads();
            p ^= 1;
            xp ^= 1;
        }
    }
}

extern "C" void kernel_launch(void* const* d_in, const int* in_sizes, int n_in,
                              void* d_out, int out_size) {
    const float* x   = (const float*)d_in[0];
    const float* AT  = (const float*)d_in[1];
    const float* KT  = (const float*)d_in[2];
    const float* CyT = (const float*)d_in[3];
    float* Y = (float*)d_out;
    (void)in_sizes; (void)n_in; (void)out_size;

    dim3 grid(NCHUNK, BB / BC, 1);   // 37 x 4 = 148 CTAs = one full wave
    dim3 block(256, 1, 1);
    rnn_scan_kernel<<<grid, block>>>(x, AT, KT, CyT, Y);
}

// round 6
// speedup vs baseline: 1.5846x; 1.5846x over previous
#include <cuda_runtime.h>
#include <cuda_fp16.h>
#include <cstdint>

#define BB   64
#define TT   4096
#define NIN  64
#define UU   128
#define NOUT 64
#define BC   16      // batch rows per CTA
#define CHUNK 111    // timesteps per chunk
#define HALO  32     // warm-up steps (rho(AT)^32 ~ 1.5e-8, far below fp16 noise)
#define NCHUNK 37    // 37*111 = 4107 >= 4096

#define XSH 36       // xbuf row stride in half2 words (32 data + 4 pad)
#define SSH 68       // sbuf row stride in half2 words (64 data + 4 pad)

__device__ __forceinline__ uint32_t h2u(__half2 h) {
    return *reinterpret_cast<uint32_t*>(&h);
}

// fp16 m16n8k16, fp32 accumulate
__device__ __forceinline__ void mma16(float c[4], const uint32_t a[4], const uint32_t b[2]) {
    asm volatile(
        "mma.sync.aligned.m16n8k16.row.col.f32.f16.f16.f32 "
        "{%0,%1,%2,%3}, {%4,%5,%6,%7}, {%8,%9}, {%0,%1,%2,%3};"
        : "+f"(c[0]), "+f"(c[1]), "+f"(c[2]), "+f"(c[3])
        : "r"(a[0]), "r"(a[1]), "r"(a[2]), "r"(a[3]), "r"(b[0]), "r"(b[1]));
}

__global__ __launch_bounds__(256, 1) void rnn_scan_kernel(
    const float* __restrict__ x,    // [B, T, NIN]
    const float* __restrict__ AT,   // [U, U]
    const float* __restrict__ KT,   // [NIN, U]
    const float* __restrict__ CyT,  // [U, NOUT]
    float* __restrict__ Y)          // [B, T, NOUT]
{
    __shared__ uint32_t sbuf[2][BC][SSH];  // state S_{t-1} as half2 (U packed), double-buffered
    __shared__ uint32_t xbuf[2][BC][XSH];  // x_t as half2, double-buffered

    const int tid  = threadIdx.x;
    const int w    = tid >> 5;
    const int lane = tid & 31;
    const int g    = lane >> 2;   // groupID (row within fragment)
    const int tig  = lane & 3;    // threadID in group

    const int t0      = blockIdx.x * CHUNK;
    const int t_end   = min(t0 + CHUNK, TT);
    const int t_start = max(0, t0 - HALO);
    const int b0      = blockIdx.y * BC;

    // ---- persistent weight fragments (fp16 half2 pairs along K, registers) ----
    // B operand col-major frag for m16n8k16: b0 = (k=16kt+2tig, 16kt+2tig+1; n=col),
    //                                        b1 = same +8 in k.
    uint32_t Af[8][2][2];   // AT: 8 k-tiles (K=128) x 2 n-tiles (warp owns 16 U-cols)
    uint32_t Kf[4][2][2];   // KT: 4 k-tiles (K=64)  x 2 n-tiles
    uint32_t Cf[8][2];      // CyT: 8 k-tiles x 1 n-tile (warp owns 8 out-cols)
    #pragma unroll
    for (int kt = 0; kt < 8; ++kt)
        #pragma unroll
        for (int nt = 0; nt < 2; ++nt) {
            int col = w * 16 + nt * 8 + g;
            int k0 = 16 * kt + 2 * tig;
            Af[kt][nt][0] = h2u(__floats2half2_rn(AT[(k0    ) * UU + col], AT[(k0 + 1) * UU + col]));
            Af[kt][nt][1] = h2u(__floats2half2_rn(AT[(k0 + 8) * UU + col], AT[(k0 + 9) * UU + col]));
        }
    #pragma unroll
    for (int kt = 0; kt < 4; ++kt)
        #pragma unroll
        for (int nt = 0; nt < 2; ++nt) {
            int col = w * 16 + nt * 8 + g;
            int k0 = 16 * kt + 2 * tig;
            Kf[kt][nt][0] = h2u(__floats2half2_rn(KT[(k0    ) * UU + col], KT[(k0 + 1) * UU + col]));
            Kf[kt][nt][1] = h2u(__floats2half2_rn(KT[(k0 + 8) * UU + col], KT[(k0 + 9) * UU + col]));
        }
    #pragma unroll
    for (int kt = 0; kt < 8; ++kt) {
        int col = w * 8 + g;
        int k0 = 16 * kt + 2 * tig;
        Cf[kt][0] = h2u(__floats2half2_rn(CyT[(k0    ) * NOUT + col], CyT[(k0 + 1) * NOUT + col]));
        Cf[kt][1] = h2u(__floats2half2_rn(CyT[(k0 + 8) * NOUT + col], CyT[(k0 + 9) * NOUT + col]));
    }

    // ---- zero initial state ----
    {
        uint32_t* z = &sbuf[0][0][0];
        for (int i = tid; i < BC * SSH; i += 256) z[i] = 0;
    }

    // ---- preload x(t_start) ----
    const int xr = tid >> 4;          // 0..15 batch row
    const int xcw = (tid & 15) * 2;   // half2 word index 0..30
    float4 xv;
    {
        int addr = ((b0 + xr) * TT + t_start) * NIN + xcw * 2;
        xv = *reinterpret_cast<const float4*>(x + addr);
        uint32_t* d = &xbuf[t_start & 1][xr][xcw];
        d[0] = h2u(__floats2half2_rn(xv.x, xv.y));
        d[1] = h2u(__floats2half2_rn(xv.z, xv.w));
    }
    __syncthreads();

    int p  = 0;                  // state buffer phase
    int xp = t_start & 1;        // x buffer phase
    for (int t = t_start; t <= t_end; ++t) {
        const bool compute_s = (t < t_end);      // block-uniform
        const bool do_y      = (t > t0);         // block-uniform

        // prefetch x(t+1)
        if (t + 1 < t_end) {
            int addr = ((b0 + xr) * TT + (t + 1)) * NIN + xcw * 2;
            xv = *reinterpret_cast<const float4*>(x + addr);
        }

        float sacc[2][4] = {{0.f,0.f,0.f,0.f},{0.f,0.f,0.f,0.f}};
        float yacc[4]    = {0.f,0.f,0.f,0.f};

        // S_t += x_t * KT   (K=64 -> 4 k16-tiles)
        if (compute_s) {
            #pragma unroll
            for (int kt = 0; kt < 4; ++kt) {
                uint32_t a[4];
                a[0] = xbuf[xp][g    ][kt * 8 + tig];
                a[1] = xbuf[xp][g + 8][kt * 8 + tig];
                a[2] = xbuf[xp][g    ][kt * 8 + tig + 4];
                a[3] = xbuf[xp][g + 8][kt * 8 + tig + 4];
                mma16(sacc[0], a, Kf[kt][0]);
                mma16(sacc[1], a, Kf[kt][1]);
            }
        }

        // S_t += S_{t-1} * AT  and  Y_{t-1} = S_{t-1} * CyT   (K=128 -> 8 k16-tiles)
        #pragma unroll
        for (int kt = 0; kt < 8; ++kt) {
            uint32_t a[4];
            a[0] = sbuf[p][g    ][kt * 8 + tig];
            a[1] = sbuf[p][g + 8][kt * 8 + tig];
            a[2] = sbuf[p][g    ][kt * 8 + tig + 4];
            a[3] = sbuf[p][g + 8][kt * 8 + tig + 4];
            if (compute_s) { mma16(sacc[0], a, Af[kt][0]); mma16(sacc[1], a, Af[kt][1]); }
            if (do_y)      { mma16(yacc, a, Cf[kt]); }
        }

        // store Y_{t-1} (fp32, direct to global)
        if (do_y) {
            int base = ((b0 + g) * TT + (t - 1)) * NOUT + w * 8 + 2 * tig;
            *reinterpret_cast<float2*>(Y + base) = make_float2(yacc[0], yacc[1]);
            *reinterpret_cast<float2*>(Y + base + 8 * TT * NOUT) = make_float2(yacc[2], yacc[3]);
        }

        if (compute_s) {
            // store S_t (half2) into the other state buffer
            // c0,c1 = (row g, cols 2tig,2tig+1 of n8-tile) -> one half2 word
            #pragma unroll
            for (int nt = 0; nt < 2; ++nt) {
                int wcol = w * 8 + nt * 4 + tig;   // half2 word index in U
                sbuf[p ^ 1][g    ][wcol] = h2u(__floats2half2_rn(sacc[nt][0], sacc[nt][1]));
                sbuf[p ^ 1][g + 8][wcol] = h2u(__floats2half2_rn(sacc[nt][2], sacc[nt][3]));
            }
            // store prefetched x(t+1)
            if (t + 1 < t_end) {
                uint32_t* d = &xbuf[xp ^ 1][xr][xcw];
                d[0] = h2u(__floats2half2_rn(xv.x, xv.y));
                d[1] = h2u(__floats2half2_rn(xv.z, xv.w));
            }
            __syncthreads();
            p ^= 1;
            xp ^= 1;
        }
    }
}

extern "C" void kernel_launch(void* const* d_in, const int* in_sizes, int n_in,
                              void* d_out, int out_size) {
    const float* x   = (const float*)d_in[0];
    const float* AT  = (const float*)d_in[1];
    const float* KT  = (const float*)d_in[2];
    const float* CyT = (const float*)d_in[3];
    float* Y = (float*)d_out;
    (void)in_sizes; (void)n_in; (void)out_size;

    dim3 grid(NCHUNK, BB / BC, 1);   // 37 x 4 = 148 CTAs = one full wave
    dim3 block(256, 1, 1);
    rnn_scan_kernel<<<grid, block>>>(x, AT, KT, CyT, Y);
}

// round 7
// speedup vs baseline: 1.7112x; 1.0799x over previous
#include <cuda_runtime.h>
#include <cuda_fp16.h>
#include <cstdint>

#define BB   64
#define TT   4096
#define NIN  64
#define UU   128
#define NOUT 64
#define BC   16       // batch rows per CTA
#define CHUNK 56      // timesteps per chunk
#define HALO  32      // warm-up (rho(AT)^32 ~ 1.5e-8 << fp16 noise)
#define NCH   74      // 74*56 = 4144 >= 4096; CTA handles chunks bx and bx+37
#define STEPS (HALO + CHUNK)   // 88; loop runs j=0..STEPS inclusive

// swizzled SMEM word index (row-major, XOR swizzle -> conflict-free frag loads, no padding)
#define SW_S(r, c) (((r) << 6) + ((c) ^ ((((r) & 7)) << 2)))   // sbuf: 64 words/row
#define SW_X(r, c) (((r) << 5) + ((c) ^ ((((r) & 7)) << 2)))   // xbuf: 32 words/row

__device__ __forceinline__ uint32_t h2u(__half2 h) {
    return *reinterpret_cast<uint32_t*>(&h);
}

// fp16 m16n8k16, fp32 accumulate
__device__ __forceinline__ void mma16(float c[4], const uint32_t a[4], const uint32_t b[2]) {
    asm volatile(
        "mma.sync.aligned.m16n8k16.row.col.f32.f16.f16.f32 "
        "{%0,%1,%2,%3}, {%4,%5,%6,%7}, {%8,%9}, {%0,%1,%2,%3};"
        : "+f"(c[0]), "+f"(c[1]), "+f"(c[2]), "+f"(c[3])
        : "r"(a[0]), "r"(a[1]), "r"(a[2]), "r"(a[3]), "r"(b[0]), "r"(b[1]));
}

__global__ __launch_bounds__(256, 1) void rnn_scan_kernel(
    const float* __restrict__ x,    // [B, T, NIN]
    const float* __restrict__ AT,   // [U, U]
    const float* __restrict__ KT,   // [NIN, U]
    const float* __restrict__ CyT,  // [U, NOUT]
    float* __restrict__ Y)          // [B, T, NOUT]
{
    // [chain][phase][...]; exactly 48 KB static total
    __shared__ uint32_t sbuf[2][2][BC * 64];   // state as half2 words, swizzled
    __shared__ uint32_t xbuf[2][2][BC * 32];   // x as half2 words, swizzled

    const int tid  = threadIdx.x;
    const int w    = tid >> 5;
    const int lane = tid & 31;
    const int g    = lane >> 2;
    const int tig  = lane & 3;

    const int t0A = blockIdx.x * CHUNK;            // chunk A: 0..36
    const int t0B = (blockIdx.x + 37) * CHUNK;     // chunk B: 37..73
    const int teA = t0A + CHUNK;                   // never clipped (max 2072)
    const int teB = min(t0B + CHUNK, TT);          // clips only for bx=36
    const int b0  = blockIdx.y * BC;

    // ---- persistent weight fragments (fp16 half2 pairs along K) ----
    uint32_t Af[8][2][2];   // AT: 8 k16-tiles x 2 n-tiles (warp owns 16 U-cols)
    uint32_t Kf[4][2][2];   // KT: 4 k16-tiles x 2 n-tiles
    uint32_t Cf[8][2];      // CyT: 8 k16-tiles x 1 n-tile (warp owns 8 out-cols)
    #pragma unroll
    for (int kt = 0; kt < 8; ++kt)
        #pragma unroll
        for (int nt = 0; nt < 2; ++nt) {
            int col = w * 16 + nt * 8 + g;
            int k0 = 16 * kt + 2 * tig;
            Af[kt][nt][0] = h2u(__floats2half2_rn(AT[(k0    ) * UU + col], AT[(k0 + 1) * UU + col]));
            Af[kt][nt][1] = h2u(__floats2half2_rn(AT[(k0 + 8) * UU + col], AT[(k0 + 9) * UU + col]));
        }
    #pragma unroll
    for (int kt = 0; kt < 4; ++kt)
        #pragma unroll
        for (int nt = 0; nt < 2; ++nt) {
            int col = w * 16 + nt * 8 + g;
            int k0 = 16 * kt + 2 * tig;
            Kf[kt][nt][0] = h2u(__floats2half2_rn(KT[(k0    ) * UU + col], KT[(k0 + 1) * UU + col]));
            Kf[kt][nt][1] = h2u(__floats2half2_rn(KT[(k0 + 8) * UU + col], KT[(k0 + 9) * UU + col]));
        }
    #pragma unroll
    for (int kt = 0; kt < 8; ++kt) {
        int col = w * 8 + g;
        int k0 = 16 * kt + 2 * tig;
        Cf[kt][0] = h2u(__floats2half2_rn(CyT[(k0    ) * NOUT + col], CyT[(k0 + 1) * NOUT + col]));
        Cf[kt][1] = h2u(__floats2half2_rn(CyT[(k0 + 8) * NOUT + col], CyT[(k0 + 9) * NOUT + col]));
    }

    // ---- zero BOTH phases of both state buffers (state at first valid t must read 0) ----
    {
        uint32_t* z = &sbuf[0][0][0];
        for (int i = tid; i < 2 * 2 * BC * 64; i += 256) z[i] = 0;
    }

    // ---- preload x at j=0 for each chain (phase 0) ----
    const int xr  = tid >> 4;          // 0..15 batch row
    const int xcw = (tid & 15) * 2;    // half2 word col 0..30
    const int tA0 = t0A - HALO;        // may be -32 for bx==0
    const int tB0 = t0B - HALO;        // always > 0
    if (tA0 >= 0) {
        float4 v = *reinterpret_cast<const float4*>(x + ((b0 + xr) * TT + tA0) * NIN + xcw * 2);
        xbuf[0][0][SW_X(xr, xcw)]     = h2u(__floats2half2_rn(v.x, v.y));
        xbuf[0][0][SW_X(xr, xcw + 1)] = h2u(__floats2half2_rn(v.z, v.w));
    }
    {
        float4 v = *reinterpret_cast<const float4*>(x + ((b0 + xr) * TT + tB0) * NIN + xcw * 2);
        xbuf[1][0][SW_X(xr, xcw)]     = h2u(__floats2half2_rn(v.x, v.y));
        xbuf[1][0][SW_X(xr, xcw + 1)] = h2u(__floats2half2_rn(v.z, v.w));
    }
    __syncthreads();

    int p = 0;
    for (int j = 0; j <= STEPS; ++j) {
        const int tA = tA0 + j;
        const int tB = tB0 + j;
        const bool csA = (tA >= 0) && (tA < teA);   // all guards block-uniform
        const bool csB = (tB < teB);
        const bool doYA = (tA > t0A) && (tA <= teA);
        const bool doYB = (tB > t0B) && (tB <= teB);
        const bool pfA = (tA + 1 >= 0) && (tA + 1 < teA);
        const bool pfB = (tB + 1 < teB);

        // prefetch x(t+1) for both chains
        float4 xvA, xvB;
        if (pfA) xvA = *reinterpret_cast<const float4*>(x + ((b0 + xr) * TT + (tA + 1)) * NIN + xcw * 2);
        if (pfB) xvB = *reinterpret_cast<const float4*>(x + ((b0 + xr) * TT + (tB + 1)) * NIN + xcw * 2);

        float sA[2][4] = {{0,0,0,0},{0,0,0,0}};
        float sB[2][4] = {{0,0,0,0},{0,0,0,0}};
        float yA[4] = {0,0,0,0};
        float yB[4] = {0,0,0,0};

        // ---- S += x*KT for both chains (independent chains interleave) ----
        #pragma unroll
        for (int kt = 0; kt < 4; ++kt) {
            if (csA) {
                uint32_t a[4];
                a[0] = xbuf[0][p][SW_X(g,     kt * 8 + tig)];
                a[1] = xbuf[0][p][SW_X(g + 8, kt * 8 + tig)];
                a[2] = xbuf[0][p][SW_X(g,     kt * 8 + tig + 4)];
                a[3] = xbuf[0][p][SW_X(g + 8, kt * 8 + tig + 4)];
                mma16(sA[0], a, Kf[kt][0]);
                mma16(sA[1], a, Kf[kt][1]);
            }
            if (csB) {
                uint32_t a[4];
                a[0] = xbuf[1][p][SW_X(g,     kt * 8 + tig)];
                a[1] = xbuf[1][p][SW_X(g + 8, kt * 8 + tig)];
                a[2] = xbuf[1][p][SW_X(g,     kt * 8 + tig + 4)];
                a[3] = xbuf[1][p][SW_X(g + 8, kt * 8 + tig + 4)];
                mma16(sB[0], a, Kf[kt][0]);
                mma16(sB[1], a, Kf[kt][1]);
            }
        }

        // ---- S += S_prev*AT and Y = S_prev*CyT, both chains ----
        #pragma unroll
        for (int kt = 0; kt < 8; ++kt) {
            {
                uint32_t a[4];
                a[0] = sbuf[0][p][SW_S(g,     kt * 8 + tig)];
                a[1] = sbuf[0][p][SW_S(g + 8, kt * 8 + tig)];
                a[2] = sbuf[0][p][SW_S(g,     kt * 8 + tig + 4)];
                a[3] = sbuf[0][p][SW_S(g + 8, kt * 8 + tig + 4)];
                if (csA)  { mma16(sA[0], a, Af[kt][0]); mma16(sA[1], a, Af[kt][1]); }
                if (doYA) { mma16(yA, a, Cf[kt]); }
            }
            {
                uint32_t a[4];
                a[0] = sbuf[1][p][SW_S(g,     kt * 8 + tig)];
                a[1] = sbuf[1][p][SW_S(g + 8, kt * 8 + tig)];
                a[2] = sbuf[1][p][SW_S(g,     kt * 8 + tig + 4)];
                a[3] = sbuf[1][p][SW_S(g + 8, kt * 8 + tig + 4)];
                if (csB)  { mma16(sB[0], a, Af[kt][0]); mma16(sB[1], a, Af[kt][1]); }
                if (doYB) { mma16(yB, a, Cf[kt]); }
            }
        }

        // ---- Y stores ----
        if (doYA) {
            int base = ((b0 + g) * TT + (tA - 1)) * NOUT + w * 8 + 2 * tig;
            *reinterpret_cast<float2*>(Y + base) = make_float2(yA[0], yA[1]);
            *reinterpret_cast<float2*>(Y + base + 8 * TT * NOUT) = make_float2(yA[2], yA[3]);
        }
        if (doYB) {
            int base = ((b0 + g) * TT + (tB - 1)) * NOUT + w * 8 + 2 * tig;
            *reinterpret_cast<float2*>(Y + base) = make_float2(yB[0], yB[1]);
            *reinterpret_cast<float2*>(Y + base + 8 * TT * NOUT) = make_float2(yB[2], yB[3]);
        }

        // ---- state + x stores into phase p^1 ----
        if (csA) {
            #pragma unroll
            for (int nt = 0; nt < 2; ++nt) {
                int wcol = w * 8 + nt * 4 + tig;
                sbuf[0][p ^ 1][SW_S(g,     wcol)] = h2u(__floats2half2_rn(sA[nt][0], sA[nt][1]));
                sbuf[0][p ^ 1][SW_S(g + 8, wcol)] = h2u(__floats2half2_rn(sA[nt][2], sA[nt][3]));
            }
        }
        if (csB) {
            #pragma unroll
            for (int nt = 0; nt < 2; ++nt) {
                int wcol = w * 8 + nt * 4 + tig;
                sbuf[1][p ^ 1][SW_S(g,     wcol)] = h2u(__floats2half2_rn(sB[nt][0], sB[nt][1]));
                sbuf[1][p ^ 1][SW_S(g + 8, wcol)] = h2u(__floats2half2_rn(sB[nt][2], sB[nt][3]));
            }
        }
        if (pfA) {
            xbuf[0][p ^ 1][SW_X(xr, xcw)]     = h2u(__floats2half2_rn(xvA.x, xvA.y));
            xbuf[0][p ^ 1][SW_X(xr, xcw + 1)] = h2u(__floats2half2_rn(xvA.z, xvA.w));
        }
        if (pfB) {
            xbuf[1][p ^ 1][SW_X(xr, xcw)]     = h2u(__floats2half2_rn(xvB.x, xvB.y));
            xbuf[1][p ^ 1][SW_X(xr, xcw + 1)] = h2u(__floats2half2_rn(xvB.z, xvB.w));
        }
        __syncthreads();
        p ^= 1;
    }
}

extern "C" void kernel_launch(void* const* d_in, const int* in_sizes, int n_in,
                              void* d_out, int out_size) {
    const float* x   = (const float*)d_in[0];
    const float* AT  = (const float*)d_in[1];
    const float* KT  = (const float*)d_in[2];
    const float* CyT = (const float*)d_in[3];
    float* Y = (float*)d_out;
    (void)in_sizes; (void)n_in; (void)out_size;

    dim3 grid(37, BB / BC, 1);   // 37 x 4 = 148 CTAs = one wave; each CTA runs 2 chunks
    dim3 block(256, 1, 1);
    rnn_scan_kernel<<<grid, block>>>(x, AT, KT, CyT, Y);
}

// round 8
// speedup vs baseline: 2.0283x; 1.1853x over previous
#include <cuda_runtime.h>
#include <cuda_fp16.h>
#include <cstdint>

#define BB   64
#define TT   4096
#define NIN  64
#define UU   128
#define NOUT 64
#define BC   16       // batch rows per CTA
#define CHUNK 56      // timesteps per chunk
#define HALO  24      // warm-up (rho(AT)^24 ~ 1.2e-6 << fp16 noise)
#define STEPS (HALO + CHUNK)   // 80; loop j = 0..STEPS inclusive

// word-unit XOR swizzle (16B-chunk granularity): conflict-free for LDSM/STSM
#define SW_X(r, c) (((r) << 5) + ((c) ^ (((r) & 7) << 2)))   // xbuf: 32 words/row

__device__ __forceinline__ uint32_t h2u(__half2 h) {
    return *reinterpret_cast<uint32_t*>(&h);
}

__device__ __forceinline__ void mma16(float c[4], const uint32_t a[4], const uint32_t b[2]) {
    asm volatile(
        "mma.sync.aligned.m16n8k16.row.col.f32.f16.f16.f32 "
        "{%0,%1,%2,%3}, {%4,%5,%6,%7}, {%8,%9}, {%0,%1,%2,%3};"
        : "+f"(c[0]), "+f"(c[1]), "+f"(c[2]), "+f"(c[3])
        : "r"(a[0]), "r"(a[1]), "r"(a[2]), "r"(a[3]), "r"(b[0]), "r"(b[1]));
}

__device__ __forceinline__ void ldsm4(uint32_t a[4], uint32_t addr) {
    asm volatile("ldmatrix.sync.aligned.m8n8.x4.shared.b16 {%0,%1,%2,%3}, [%4];"
        : "=r"(a[0]), "=r"(a[1]), "=r"(a[2]), "=r"(a[3]) : "r"(addr));
}

__device__ __forceinline__ void stsm4(uint32_t addr, uint32_t r0, uint32_t r1,
                                      uint32_t r2, uint32_t r3) {
    asm volatile("stmatrix.sync.aligned.m8n8.x4.shared.b16 [%0], {%1,%2,%3,%4};"
        :: "r"(addr), "r"(r0), "r"(r1), "r"(r2), "r"(r3) : "memory");
}

__global__ __launch_bounds__(256, 1) void rnn_scan_kernel(
    const float* __restrict__ x,    // [B, T, NIN]
    const float* __restrict__ AT,   // [U, U]
    const float* __restrict__ KT,   // [NIN, U]
    const float* __restrict__ CyT,  // [U, NOUT]
    float* __restrict__ Y)          // [B, T, NOUT]
{
    // [chain][phase][...] ; 24 KB static
    __shared__ uint32_t sbuf[2][2][BC * 64];   // state half2 words, swizzled (256B rows)
    __shared__ uint32_t xbuf[2][2][BC * 32];   // x half2 words, swizzled (128B rows)

    const int tid  = threadIdx.x;
    const int w    = tid >> 5;
    const int lane = tid & 31;
    const int g    = lane >> 2;
    const int tig  = lane & 3;

    const int t0A = blockIdx.x * CHUNK;            // chunks 0..36
    const int t0B = (blockIdx.x + 37) * CHUNK;     // chunks 37..73
    const int teA = t0A + CHUNK;                   // <= 2072, never clipped
    const int teB = min(t0B + CHUNK, TT);          // clips only at bx=36
    const int b0  = blockIdx.y * BC;

    // ---- persistent weight fragments (fp16 half2 pairs along K) ----
    uint32_t Af[8][2][2], Kf[4][2][2], Cf[8][2];
    #pragma unroll
    for (int kt = 0; kt < 8; ++kt)
        #pragma unroll
        for (int nt = 0; nt < 2; ++nt) {
            int col = w * 16 + nt * 8 + g;
            int k0 = 16 * kt + 2 * tig;
            Af[kt][nt][0] = h2u(__floats2half2_rn(AT[(k0    ) * UU + col], AT[(k0 + 1) * UU + col]));
            Af[kt][nt][1] = h2u(__floats2half2_rn(AT[(k0 + 8) * UU + col], AT[(k0 + 9) * UU + col]));
        }
    #pragma unroll
    for (int kt = 0; kt < 4; ++kt)
        #pragma unroll
        for (int nt = 0; nt < 2; ++nt) {
            int col = w * 16 + nt * 8 + g;
            int k0 = 16 * kt + 2 * tig;
            Kf[kt][nt][0] = h2u(__floats2half2_rn(KT[(k0    ) * UU + col], KT[(k0 + 1) * UU + col]));
            Kf[kt][nt][1] = h2u(__floats2half2_rn(KT[(k0 + 8) * UU + col], KT[(k0 + 9) * UU + col]));
        }
    #pragma unroll
    for (int kt = 0; kt < 8; ++kt) {
        int col = w * 8 + g;
        int k0 = 16 * kt + 2 * tig;
        Cf[kt][0] = h2u(__floats2half2_rn(CyT[(k0    ) * NOUT + col], CyT[(k0 + 1) * NOUT + col]));
        Cf[kt][1] = h2u(__floats2half2_rn(CyT[(k0 + 8) * NOUT + col], CyT[(k0 + 9) * NOUT + col]));
    }

    // ---- ldmatrix/stmatrix per-thread address components ----
    const int srow = lane & 15;               // fragment row
    const int cofs = (lane >> 4) << 2;        // 0 or 4 words (k/col-half select)
    const int sw   = (srow & 7) << 2;         // row swizzle (words)
    const int boffS = srow * 256 + ((cofs ^ (sw & 4)) << 2);  // sbuf byte offset (row stride 256B)
    const int boffX = srow * 128 + ((cofs ^ (sw & 4)) << 2);  // xbuf byte offset (row stride 128B)
    const int sxs   = (sw & 24) << 2;         // byte-XOR applied to the kt/w column term

    const uint32_t sA0 = (uint32_t)__cvta_generic_to_shared(&sbuf[0][0][0]);
    const uint32_t sA1 = (uint32_t)__cvta_generic_to_shared(&sbuf[0][1][0]);
    const uint32_t sB0 = (uint32_t)__cvta_generic_to_shared(&sbuf[1][0][0]);
    const uint32_t sB1 = (uint32_t)__cvta_generic_to_shared(&sbuf[1][1][0]);
    const uint32_t xA0 = (uint32_t)__cvta_generic_to_shared(&xbuf[0][0][0]);
    const uint32_t xA1 = (uint32_t)__cvta_generic_to_shared(&xbuf[0][1][0]);
    const uint32_t xB0 = (uint32_t)__cvta_generic_to_shared(&xbuf[1][0][0]);
    const uint32_t xB1 = (uint32_t)__cvta_generic_to_shared(&xbuf[1][1][0]);

    // ---- zero all state buffers (both phases) ----
    {
        uint32_t* z = &sbuf[0][0][0];
        for (int i = tid; i < 2 * 2 * BC * 64; i += 256) z[i] = 0;
    }

    // ---- preload x at j=0 (phase 0) ----
    const int xr  = tid >> 4;
    const int xcw = (tid & 15) * 2;
    const int tA0 = t0A - HALO;   // may be -24 for bx==0
    const int tB0 = t0B - HALO;   // always > 0
    if (tA0 >= 0) {
        float4 v = *reinterpret_cast<const float4*>(x + ((b0 + xr) * TT + tA0) * NIN + xcw * 2);
        *reinterpret_cast<uint2*>(&xbuf[0][0][SW_X(xr, xcw)]) =
            make_uint2(h2u(__floats2half2_rn(v.x, v.y)), h2u(__floats2half2_rn(v.z, v.w)));
    }
    {
        float4 v = *reinterpret_cast<const float4*>(x + ((b0 + xr) * TT + tB0) * NIN + xcw * 2);
        *reinterpret_cast<uint2*>(&xbuf[1][0][SW_X(xr, xcw)]) =
            make_uint2(h2u(__floats2half2_rn(v.x, v.y)), h2u(__floats2half2_rn(v.z, v.w)));
    }
    __syncthreads();

    int p = 0;
    for (int j = 0; j <= STEPS; ++j) {
        const int tA = tA0 + j;
        const int tB = tB0 + j;
        const bool csA  = (tA >= 0) && (tA < teA);
        const bool csB  = (tB < teB);
        const bool doYA = (tA > t0A) && (tA <= teA);
        const bool doYB = (tB > t0B) && (tB <= teB);
        const bool pfA  = (tA + 1 >= 0) && (tA + 1 < teA);
        const bool pfB  = (tB + 1 < teB);

        const uint32_t sRA = p ? sA1 : sA0;   // state read bases
        const uint32_t sRB = p ? sB1 : sB0;
        const uint32_t sWA = p ? sA0 : sA1;   // state write bases
        const uint32_t sWB = p ? sB0 : sB1;
        const uint32_t xRA = p ? xA1 : xA0;
        const uint32_t xRB = p ? xB1 : xB0;

        float4 xvA, xvB;
        if (pfA) xvA = *reinterpret_cast<const float4*>(x + ((b0 + xr) * TT + (tA + 1)) * NIN + xcw * 2);
        if (pfB) xvB = *reinterpret_cast<const float4*>(x + ((b0 + xr) * TT + (tB + 1)) * NIN + xcw * 2);

        float sA[2][4] = {{0,0,0,0},{0,0,0,0}};
        float sB[2][4] = {{0,0,0,0},{0,0,0,0}};
        float yA[4] = {0,0,0,0};
        float yB[4] = {0,0,0,0};

        // ---- S += x*KT (4 k16-tiles) ----
        #pragma unroll
        for (int kt = 0; kt < 4; ++kt) {
            const uint32_t koff = (uint32_t)((kt << 5) ^ sxs);
            if (csA) {
                uint32_t a[4];
                ldsm4(a, xRA + boffX + koff);
                mma16(sA[0], a, Kf[kt][0]);
                mma16(sA[1], a, Kf[kt][1]);
            }
            if (csB) {
                uint32_t a[4];
                ldsm4(a, xRB + boffX + koff);
                mma16(sB[0], a, Kf[kt][0]);
                mma16(sB[1], a, Kf[kt][1]);
            }
        }

        // ---- S += S_prev*AT ; Y = S_prev*CyT (8 k16-tiles) ----
        #pragma unroll
        for (int kt = 0; kt < 8; ++kt) {
            const uint32_t koff = (uint32_t)((kt << 5) ^ sxs);
            {
                uint32_t a[4];
                ldsm4(a, sRA + boffS + koff);
                if (csA)  { mma16(sA[0], a, Af[kt][0]); mma16(sA[1], a, Af[kt][1]); }
                if (doYA) { mma16(yA, a, Cf[kt]); }
            }
            {
                uint32_t a[4];
                ldsm4(a, sRB + boffS + koff);
                if (csB)  { mma16(sB[0], a, Af[kt][0]); mma16(sB[1], a, Af[kt][1]); }
                if (doYB) { mma16(yB, a, Cf[kt]); }
            }
        }

        // ---- Y stores ----
        if (doYA) {
            int base = ((b0 + g) * TT + (tA - 1)) * NOUT + w * 8 + 2 * tig;
            *reinterpret_cast<float2*>(Y + base) = make_float2(yA[0], yA[1]);
            *reinterpret_cast<float2*>(Y + base + 8 * TT * NOUT) = make_float2(yA[2], yA[3]);
        }
        if (doYB) {
            int base = ((b0 + g) * TT + (tB - 1)) * NOUT + w * 8 + 2 * tig;
            *reinterpret_cast<float2*>(Y + base) = make_float2(yB[0], yB[1]);
            *reinterpret_cast<float2*>(Y + base + 8 * TT * NOUT) = make_float2(yB[2], yB[3]);
        }

        // ---- state stores via stmatrix (one x4 per chain) ----
        const uint32_t woff = (uint32_t)((w << 5) ^ sxs);
        if (csA) {
            stsm4(sWA + boffS + woff,
                  h2u(__floats2half2_rn(sA[0][0], sA[0][1])),
                  h2u(__floats2half2_rn(sA[0][2], sA[0][3])),
                  h2u(__floats2half2_rn(sA[1][0], sA[1][1])),
                  h2u(__floats2half2_rn(sA[1][2], sA[1][3])));
        }
        if (csB) {
            stsm4(sWB + boffS + woff,
                  h2u(__floats2half2_rn(sB[0][0], sB[0][1])),
                  h2u(__floats2half2_rn(sB[0][2], sB[0][3])),
                  h2u(__floats2half2_rn(sB[1][0], sB[1][1])),
                  h2u(__floats2half2_rn(sB[1][2], sB[1][3])));
        }
        // ---- x stores (phase p^1) ----
        if (pfA) {
            *reinterpret_cast<uint2*>(&xbuf[0][p ^ 1][SW_X(xr, xcw)]) =
                make_uint2(h2u(__floats2half2_rn(xvA.x, xvA.y)), h2u(__floats2half2_rn(xvA.z, xvA.w)));
        }
        if (pfB) {
            *reinterpret_cast<uint2*>(&xbuf[1][p ^ 1][SW_X(xr, xcw)]) =
                make_uint2(h2u(__floats2half2_rn(xvB.x, xvB.y)), h2u(__floats2half2_rn(xvB.z, xvB.w)));
        }
        __syncthreads();
        p ^= 1;
    }
}

extern "C" void kernel_launch(void* const* d_in, const int* in_sizes, int n_in,
                              void* d_out, int out_size) {
    const float* x   = (const float*)d_in[0];
    const float* AT  = (const float*)d_in[1];
    const float* KT  = (const float*)d_in[2];
    const float* CyT = (const float*)d_in[3];
    float* Y = (float*)d_out;
    (void)in_sizes; (void)n_in; (void)out_size;

    dim3 grid(37, BB / BC, 1);   // 148 CTAs = one wave; each CTA runs chunks bx and bx+37
    dim3 block(256, 1, 1);
    rnn_scan_kernel<<<grid, block>>>(x, AT, KT, CyT, Y);
}